// round 1
// baseline (speedup 1.0000x reference)
#include <cuda_runtime.h>
#include <math.h>

// ---------------------------------------------------------------------------
// EncoderLayer sparse U-Net (B=4, D=64, C=16, NS=4), dense-emulated with
// active-site compaction. fp32 throughout.
// Output: [hidden (4*8192) | out (4*64^3)] = 1,081,344 floats.
// ---------------------------------------------------------------------------

#define CDIV(a,b) (((a)+(b)-1)/(b))

#define Bn 4
#define Cn 16
#define GBN 128

#define NS0 (4*64*64*64)   // 1048576 sites at 64^3
#define NS1 (4*32*32*32)   // 131072
#define NS2 (4*16*16*16)   // 16384
#define NS3 (4*8*8*8)      // 2048
#define LXC (Bn*Cn*64*64*64) // 16777216 floats (full 16-ch 64^3 tensor)

// float scratch arena offsets
#define OFF_XA 0L
#define OFF_XB (OFF_XA + LXC)
#define OFF_M0 (OFF_XB + LXC)
#define OFF_M1 (OFF_M0 + NS0)
#define OFF_M2 (OFF_M1 + NS1)
#define OFF_M3 (OFF_M2 + NS2)
#define MEM_TOTAL (OFF_M3 + NS3)

__device__ float  g_mem[MEM_TOTAL];
__device__ int    g_list[NS0 + NS1 + NS2 + NS3];
#define LOFF0 0
#define LOFF1 (NS0)
#define LOFF2 (NS0+NS1)
#define LOFF3 (NS0+NS1+NS2)
__device__ int    g_cnt[4];
__device__ double g_psum[GBN*Cn];
__device__ double g_psq [GBN*Cn];
__device__ double g_pcnt[GBN];
__device__ float  g_A[Cn];
__device__ float  g_Bb[Cn];

// ------------------------------- elementwise -------------------------------

__global__ void k_zero(long off, int n) {
    float* p = g_mem + off;
    for (int i = blockIdx.x*blockDim.x + threadIdx.x; i < n; i += gridDim.x*blockDim.x)
        p[i] = 0.f;
}

__global__ void k_reset(int idx) { if (threadIdx.x == 0) g_cnt[idx] = 0; }

__global__ void k_scatter(const float* __restrict__ data, const int* __restrict__ cid, int n) {
    int i = blockIdx.x*blockDim.x + threadIdx.x;
    if (i >= n) return;
    int z = (int)data[i*5+0];
    int y = (int)data[i*5+1];
    int x = (int)data[i*5+2];
    int b = cid[i];
    atomicAdd(&g_mem[OFF_XA + ((((long)b*64 + z)*64 + y)*64 + x)], 1.0f);
}

// mask[i] = src[i] > 0 ; append active sites to list
__global__ void k_mask_list(long srcoff, long moff, int loff, int cidx, int n) {
    int i = blockIdx.x*blockDim.x + threadIdx.x;
    if (i >= n) return;
    bool a = g_mem[srcoff + i] > 0.f;
    g_mem[moff + i] = a ? 1.f : 0.f;
    if (a) {
        int p = atomicAdd(&g_cnt[cidx], 1);
        g_list[loff + p] = i;
    }
}

// out mask at size S from in mask at size 2S (2x2x2 any-active)
__global__ void k_downmask(long inoff, long outoff, int S) {
    int n = Bn*S*S*S;
    int i = blockIdx.x*blockDim.x + threadIdx.x;
    if (i >= n) return;
    int S2 = S*S, S3 = S2*S;
    int b = i / S3; int r = i - b*S3;
    int z = r / S2; r -= z*S2;
    int y = r / S;  int x = r - y*S;
    int Si = 2*S, Si2 = Si*Si, Si3 = Si2*Si;
    const float* mi = g_mem + inoff + (long)b*Si3;
    float any = 0.f;
#pragma unroll
    for (int a = 0; a < 2; a++)
#pragma unroll
        for (int bb = 0; bb < 2; bb++)
#pragma unroll
            for (int c = 0; c < 2; c++) {
                float v = mi[(2*z+a)*Si2 + (2*y+bb)*Si + (2*x+c)];
                any = fmaxf(any, v);
            }
    g_mem[outoff + i] = any > 0.f ? 1.f : 0.f;
}

// m[i] = m[i] * (x[b, ch0, site] > 0)
__global__ void k_sparsify(long moff, long xoff, int S3) {
    int n = Bn*S3;
    int i = blockIdx.x*blockDim.x + threadIdx.x;
    if (i >= n) return;
    int b = i / S3; int sp = i - b*S3;
    float v = g_mem[xoff + (long)(b*Cn)*S3 + sp];
    float m = g_mem[moff + i];
    g_mem[moff + i] = (m > 0.f && v > 0.f) ? 1.f : 0.f;
}

// x *= mask (dense over all channels)
__global__ void k_maskmul(long xoff, long moff, int S3) {
    int n = Bn*Cn*S3;
    for (int i = blockIdx.x*blockDim.x + threadIdx.x; i < n; i += gridDim.x*blockDim.x) {
        int cs = i / S3; int sp = i - cs*S3;
        int b = cs / Cn;
        g_mem[xoff + i] *= g_mem[moff + b*S3 + sp];
    }
}

__global__ void k_copy(float* __restrict__ dst, long srcoff, int n) {
    for (int i = blockIdx.x*blockDim.x + threadIdx.x; i < n; i += gridDim.x*blockDim.x)
        dst[i] = g_mem[srcoff + i];
}

// ------------------------------- BatchNorm ---------------------------------

__global__ void k_bn_part(long xoff, long moff, int S3) {
    const float* x = g_mem + xoff;
    const float* m = g_mem + moff;
    int c = blockIdx.y;
    int total = Bn*S3;
    double s = 0.0, q = 0.0, n = 0.0;
    for (int i = blockIdx.x*blockDim.x + threadIdx.x; i < total; i += gridDim.x*blockDim.x) {
        float mk = m[i];
        if (mk != 0.f) {
            int b = i / S3; int sp = i - b*S3;
            float v = x[(b*Cn + c)*S3 + sp];
            s += (double)v;
            q += (double)v * (double)v;
            n += 1.0;
        }
    }
    __shared__ double sh[256];
    int t = threadIdx.x;
    sh[t] = s; __syncthreads();
    for (int o = 128; o > 0; o >>= 1) { if (t < o) sh[t] += sh[t+o]; __syncthreads(); }
    if (t == 0) g_psum[c*gridDim.x + blockIdx.x] = sh[0];
    __syncthreads();
    sh[t] = q; __syncthreads();
    for (int o = 128; o > 0; o >>= 1) { if (t < o) sh[t] += sh[t+o]; __syncthreads(); }
    if (t == 0) g_psq[c*gridDim.x + blockIdx.x] = sh[0];
    if (c == 0) {
        __syncthreads();
        sh[t] = n; __syncthreads();
        for (int o = 128; o > 0; o >>= 1) { if (t < o) sh[t] += sh[t+o]; __syncthreads(); }
        if (t == 0) g_pcnt[blockIdx.x] = sh[0];
    }
}

__global__ void k_bn_fin(const float* __restrict__ gamma, const float* __restrict__ beta) {
    __shared__ double ncnt;
    if (threadIdx.x == 0) {
        double n = 0.0;
        for (int g = 0; g < GBN; g++) n += g_pcnt[g];
        ncnt = n < 1.0 ? 1.0 : n;
    }
    __syncthreads();
    int c = threadIdx.x;
    if (c < Cn) {
        double s = 0.0, q = 0.0;
        for (int g = 0; g < GBN; g++) { s += g_psum[c*GBN + g]; q += g_psq[c*GBN + g]; }
        double mean = s / ncnt;
        double var  = q / ncnt - mean*mean;
        double inv  = 1.0 / sqrt(var + 1e-4);
        double A    = (double)gamma[c] * inv;
        g_A[c]  = (float)A;
        g_Bb[c] = (float)((double)beta[c] - mean*A);
    }
}

// x = relu(x*A + B) * mask  (LEAK=0)
__global__ void k_bn_apply(long xoff, long moff, int S3) {
    int n = Bn*Cn*S3;
    for (int i = blockIdx.x*blockDim.x + threadIdx.x; i < n; i += gridDim.x*blockDim.x) {
        int cs = i / S3; int sp = i - cs*S3;
        int b = cs / Cn; int c = cs - b*Cn;
        float mk = g_mem[moff + b*S3 + sp];
        float v  = g_mem[xoff + i] * g_A[c] + g_Bb[c];
        g_mem[xoff + i] = (v > 0.f ? v : 0.f) * mk;
    }
}

// ------------------------------- convolutions ------------------------------

// k=3, pad=1 submanifold conv over active list
template<int CIN, int COUT>
__global__ void k_conv3(long inoff, long outoff, const float* __restrict__ w,
                        int loff, int cidx, int S) {
    if (blockIdx.x * blockDim.x >= g_cnt[cidx]) return;
    __shared__ __align__(16) float sw[27*CIN*COUT];
    for (int i = threadIdx.x; i < 27*CIN*COUT; i += blockDim.x) sw[i] = w[i];
    __syncthreads();
    int idx = blockIdx.x*blockDim.x + threadIdx.x;
    if (idx >= g_cnt[cidx]) return;
    int site = g_list[loff + idx];
    const float* in = g_mem + inoff;
    float* out = g_mem + outoff;
    int S2 = S*S, S3 = S2*S;
    int b = site / S3; int r = site - b*S3;
    int z = r / S2; r -= z*S2;
    int y = r / S;  int x = r - y*S;
    float acc[COUT];
#pragma unroll
    for (int co = 0; co < COUT; co++) acc[co] = 0.f;
#pragma unroll 1
    for (int dz = 0; dz < 3; dz++) {
        int zz = z + dz - 1; if ((unsigned)zz >= (unsigned)S) continue;
#pragma unroll 1
        for (int dy = 0; dy < 3; dy++) {
            int yy = y + dy - 1; if ((unsigned)yy >= (unsigned)S) continue;
#pragma unroll
            for (int dx = 0; dx < 3; dx++) {
                int xx = x + dx - 1; if ((unsigned)xx >= (unsigned)S) continue;
                const float* ip = in + (b*CIN)*S3 + zz*S2 + yy*S + xx;
                const float* wp = sw + (((dz*3 + dy)*3 + dx)*CIN)*COUT;
#pragma unroll
                for (int ci = 0; ci < CIN; ci++) {
                    float v = ip[ci*S3];
                    const float* wc = wp + ci*COUT;
#pragma unroll
                    for (int co = 0; co < COUT; co++) acc[co] += v * wc[co];
                }
            }
        }
    }
    float* op = out + (b*COUT)*S3 + z*S2 + y*S + x;
#pragma unroll
    for (int co = 0; co < COUT; co++) op[co*S3] = acc[co];
}

// k=4, pad=(1,2) submanifold conv (16->16); weights streamed by dz-slice (16KB smem)
__global__ void k_conv4(long inoff, long outoff, const float* __restrict__ w,
                        int loff, int cidx, int S) {
    if (blockIdx.x * blockDim.x >= g_cnt[cidx]) return;
    __shared__ __align__(16) float sw[16*Cn*Cn]; // one dz slice: 4*4*16*16 = 4096 floats
    int idx = blockIdx.x*blockDim.x + threadIdx.x;
    bool act = idx < g_cnt[cidx];
    int site = act ? g_list[loff + idx] : 0;
    const float* in = g_mem + inoff;
    float* out = g_mem + outoff;
    int S2 = S*S, S3 = S2*S;
    int b = site / S3; int r = site - b*S3;
    int z = r / S2; r -= z*S2;
    int y = r / S;  int x = r - y*S;
    float acc[Cn];
#pragma unroll
    for (int co = 0; co < Cn; co++) acc[co] = 0.f;
#pragma unroll 1
    for (int dz = 0; dz < 4; dz++) {
        __syncthreads();
        for (int i = threadIdx.x; i < 16*Cn*Cn; i += blockDim.x) sw[i] = w[dz*16*Cn*Cn + i];
        __syncthreads();
        int zz = z + dz - 1;
        if (act && (unsigned)zz < (unsigned)S) {
#pragma unroll 1
            for (int dy = 0; dy < 4; dy++) {
                int yy = y + dy - 1; if ((unsigned)yy >= (unsigned)S) continue;
#pragma unroll
                for (int dx = 0; dx < 4; dx++) {
                    int xx = x + dx - 1; if ((unsigned)xx >= (unsigned)S) continue;
                    const float* ip = in + (b*Cn)*S3 + zz*S2 + yy*S + xx;
                    const float* wp = sw + ((dy*4 + dx)*Cn)*Cn;
#pragma unroll
                    for (int ci = 0; ci < Cn; ci++) {
                        float v = ip[ci*S3];
                        const float* wc = wp + ci*Cn;
#pragma unroll
                        for (int co = 0; co < Cn; co++) acc[co] += v * wc[co];
                    }
                }
            }
        }
    }
    if (act) {
        float* op = out + (b*Cn)*S3 + z*S2 + y*S + x;
#pragma unroll
        for (int co = 0; co < Cn; co++) op[co*S3] = acc[co];
    }
}

// strided k=2 s=2 downsampling conv; S = output size, input at 2S, list on new mask
__global__ void k_down(long inoff, long outoff, const float* __restrict__ w,
                       int loff, int cidx, int S) {
    if (blockIdx.x * blockDim.x >= g_cnt[cidx]) return;
    __shared__ __align__(16) float sw[8*Cn*Cn];
    for (int i = threadIdx.x; i < 8*Cn*Cn; i += blockDim.x) sw[i] = w[i];
    __syncthreads();
    int idx = blockIdx.x*blockDim.x + threadIdx.x;
    if (idx >= g_cnt[cidx]) return;
    int site = g_list[loff + idx];
    const float* in = g_mem + inoff;
    float* out = g_mem + outoff;
    int S2 = S*S, S3 = S2*S;
    int b = site / S3; int r = site - b*S3;
    int z = r / S2; r -= z*S2;
    int y = r / S;  int x = r - y*S;
    int Si = 2*S, Si2 = Si*Si, Si3 = Si2*Si;
    float acc[Cn];
#pragma unroll
    for (int co = 0; co < Cn; co++) acc[co] = 0.f;
#pragma unroll 1
    for (int a = 0; a < 2; a++)
#pragma unroll 1
        for (int bb = 0; bb < 2; bb++)
#pragma unroll
            for (int c = 0; c < 2; c++) {
                const float* ip = in + (b*Cn)*Si3 + (2*z+a)*Si2 + (2*y+bb)*Si + (2*x+c);
                const float* wp = sw + (((a*2 + bb)*2 + c)*Cn)*Cn;
#pragma unroll
                for (int ci = 0; ci < Cn; ci++) {
                    float v = ip[ci*Si3];
                    const float* wc = wp + ci*Cn;
#pragma unroll
                    for (int co = 0; co < Cn; co++) acc[co] += v * wc[co];
                }
            }
    float* op = out + (b*Cn)*S3 + z*S2 + y*S + x;
#pragma unroll
    for (int co = 0; co < Cn; co++) op[co*S3] = acc[co];
}

// conv_transpose k=2 s=2 VALID: out[2m+a] uses w[1-a]; S = output size, input at S/2
__global__ void k_up(long inoff, long outoff, const float* __restrict__ w,
                     int loff, int cidx, int S) {
    if (blockIdx.x * blockDim.x >= g_cnt[cidx]) return;
    __shared__ __align__(16) float sw[8*Cn*Cn];
    for (int i = threadIdx.x; i < 8*Cn*Cn; i += blockDim.x) sw[i] = w[i];
    __syncthreads();
    int idx = blockIdx.x*blockDim.x + threadIdx.x;
    if (idx >= g_cnt[cidx]) return;
    int site = g_list[loff + idx];
    const float* in = g_mem + inoff;
    float* out = g_mem + outoff;
    int S2 = S*S, S3 = S2*S;
    int b = site / S3; int r = site - b*S3;
    int z = r / S2; r -= z*S2;
    int y = r / S;  int x = r - y*S;
    int Sh = S >> 1, Sh2 = Sh*Sh, Sh3 = Sh2*Sh;
    int tz = 1 - (z & 1), ty = 1 - (y & 1), tx = 1 - (x & 1);
    const float* wp = sw + (((tz*2 + ty)*2 + tx)*Cn)*Cn;
    const float* ip = in + (b*Cn)*Sh3 + (z >> 1)*Sh2 + (y >> 1)*Sh + (x >> 1);
    float acc[Cn];
#pragma unroll
    for (int co = 0; co < Cn; co++) acc[co] = 0.f;
#pragma unroll
    for (int ci = 0; ci < Cn; ci++) {
        float v = ip[ci*Sh3];
        const float* wc = wp + ci*Cn;
#pragma unroll
        for (int co = 0; co < Cn; co++) acc[co] += v * wc[co];
    }
    float* op = out + (b*Cn)*S3 + z*S2 + y*S + x;
#pragma unroll
    for (int co = 0; co < Cn; co++) op[co*S3] = acc[co];
}

// ------------------------------- host --------------------------------------

static void bn_stage(long xoff, long moff, int S3, const float* gamma, const float* beta) {
    dim3 gp(GBN, Cn);
    k_bn_part<<<gp, 256>>>(xoff, moff, S3);
    k_bn_fin<<<1, 32>>>(gamma, beta);
    int total = Bn*Cn*S3;
    int g = CDIV(total, 256); if (g > 8192) g = 8192;
    k_bn_apply<<<g, 256>>>(xoff, moff, S3);
}

static void build_list(long srcoff, long moff, int loff, int cidx, int n) {
    k_reset<<<1, 1>>>(cidx);
    k_mask_list<<<CDIV(n, 256), 256>>>(srcoff, moff, loff, cidx, n);
}

extern "C" void kernel_launch(void* const* d_in, const int* in_sizes, int n_in,
                              void* d_out, int out_size) {
    const float* data      = (const float*)d_in[0];
    const int*   cid       = (const int*)  d_in[1];
    const float* w_prep    = (const float*)d_in[2];
    const float* enc_gamma = (const float*)d_in[3];
    const float* enc_beta  = (const float*)d_in[4];
    const float* enc_wsub  = (const float*)d_in[5];
    const float* enc_wdown = (const float*)d_in[6];
    const float* dec_gamma = (const float*)d_in[7];
    const float* dec_beta  = (const float*)d_in[8];
    const float* dec_wup   = (const float*)d_in[9];
    const float* dec_wsub3 = (const float*)d_in[10];
    const float* dec_wsub4 = (const float*)d_in[11];
    const float* w_out     = (const float*)d_in[12];
    float* outp = (float*)d_out;
    int npts = in_sizes[0] / 5;
    const int T = 256;
    (void)n_in; (void)out_size;

    // ---- input scatter (counts) + level-0 mask/list ----
    k_zero<<<2048, T>>>(OFF_XA, NS0);
    k_scatter<<<CDIV(npts, T), T>>>(data, cid, npts);
    build_list(OFF_XA, OFF_M0, LOFF0, 0, NS0);

    // ---- prepare: SubmanifoldConv(1->16, k3) ----
    k_zero<<<8192, T>>>(OFF_XB, LXC);
    k_conv3<1, Cn><<<CDIV(NS0, T), T>>>(OFF_XA, OFF_XB, w_prep, LOFF0, 0, 64);

    // ---- encoder stage 0 (64^3 -> 32^3) ----
    bn_stage(OFF_XB, OFF_M0, 64*64*64, enc_gamma + 0, enc_beta + 0);
    k_zero<<<8192, T>>>(OFF_XA, LXC);
    k_conv3<Cn, Cn><<<CDIV(NS0, T), T>>>(OFF_XB, OFF_XA, enc_wsub + 0, LOFF0, 0, 64);
    k_downmask<<<CDIV(NS1, T), T>>>(OFF_M0, OFF_M1, 32);
    build_list(OFF_M1, OFF_M1, LOFF1, 1, NS1);
    k_zero<<<2048, T>>>(OFF_XB, Cn*NS1);
    k_down<<<CDIV(NS1, T), T>>>(OFF_XA, OFF_XB, enc_wdown + 0, LOFF1, 1, 32);

    // ---- encoder stage 1 (32^3 -> 16^3) ----
    bn_stage(OFF_XB, OFF_M1, 32*32*32, enc_gamma + 16, enc_beta + 16);
    k_zero<<<2048, T>>>(OFF_XA, Cn*NS1);
    k_conv3<Cn, Cn><<<CDIV(NS1, T), T>>>(OFF_XB, OFF_XA, enc_wsub + 6912, LOFF1, 1, 32);
    k_downmask<<<CDIV(NS2, T), T>>>(OFF_M1, OFF_M2, 16);
    build_list(OFF_M2, OFF_M2, LOFF2, 2, NS2);
    k_zero<<<512, T>>>(OFF_XB, Cn*NS2);
    k_down<<<CDIV(NS2, T), T>>>(OFF_XA, OFF_XB, enc_wdown + 2048, LOFF2, 2, 16);

    // ---- encoder stage 2 (16^3 -> 8^3) ----
    bn_stage(OFF_XB, OFF_M2, 16*16*16, enc_gamma + 32, enc_beta + 32);
    k_zero<<<512, T>>>(OFF_XA, Cn*NS2);
    k_conv3<Cn, Cn><<<CDIV(NS2, T), T>>>(OFF_XB, OFF_XA, enc_wsub + 13824, LOFF2, 2, 16);
    k_downmask<<<CDIV(NS3, T), T>>>(OFF_M2, OFF_M3, 8);
    build_list(OFF_M3, OFF_M3, LOFF3, 3, NS3);
    k_zero<<<128, T>>>(OFF_XB, Cn*NS3);
    k_down<<<CDIV(NS3, T), T>>>(OFF_XA, OFF_XB, enc_wdown + 4096, LOFF3, 3, 8);

    // ---- hidden output (x3 flattened = NCDHW layout) ----
    k_copy<<<CDIV(Cn*NS3, T), T>>>(outp, OFF_XB, Cn*NS3);

    // ---- decoder stage j=0 (lvl 2: 8^3 -> 16^3) ----
    bn_stage(OFF_XB, OFF_M3, 8*8*8, dec_gamma + 0, dec_beta + 0);
    k_zero<<<512, T>>>(OFF_XA, Cn*NS2);
    k_up<<<CDIV(NS2, T), T>>>(OFF_XB, OFF_XA, dec_wup + 0, LOFF2, 2, 16);
    k_zero<<<512, T>>>(OFF_XB, Cn*NS2);
    k_conv3<Cn, Cn><<<CDIV(NS2, T), T>>>(OFF_XA, OFF_XB, dec_wsub3 + 0, LOFF2, 2, 16);
    k_sparsify<<<CDIV(NS2, T), T>>>(OFF_M2, OFF_XB, 16*16*16);
    k_maskmul<<<CDIV(Cn*NS2, T), T>>>(OFF_XB, OFF_M2, 16*16*16);
    build_list(OFF_M2, OFF_M2, LOFF2, 2, NS2);
    k_zero<<<512, T>>>(OFF_XA, Cn*NS2);
    k_conv4<<<CDIV(NS2, T), T>>>(OFF_XB, OFF_XA, dec_wsub4 + 0, LOFF2, 2, 16);

    // ---- decoder stage j=1 (lvl 1: 16^3 -> 32^3) ----
    bn_stage(OFF_XA, OFF_M2, 16*16*16, dec_gamma + 16, dec_beta + 16);
    k_zero<<<2048, T>>>(OFF_XB, Cn*NS1);
    k_up<<<CDIV(NS1, T), T>>>(OFF_XA, OFF_XB, dec_wup + 2048, LOFF1, 1, 32);
    k_zero<<<2048, T>>>(OFF_XA, Cn*NS1);
    k_conv3<Cn, Cn><<<CDIV(NS1, T), T>>>(OFF_XB, OFF_XA, dec_wsub3 + 6912, LOFF1, 1, 32);
    k_sparsify<<<CDIV(NS1, T), T>>>(OFF_M1, OFF_XA, 32*32*32);
    k_maskmul<<<CDIV(Cn*NS1, T), T>>>(OFF_XA, OFF_M1, 32*32*32);
    build_list(OFF_M1, OFF_M1, LOFF1, 1, NS1);
    k_zero<<<2048, T>>>(OFF_XB, Cn*NS1);
    k_conv4<<<CDIV(NS1, T), T>>>(OFF_XA, OFF_XB, dec_wsub4 + 16384, LOFF1, 1, 32);

    // ---- decoder stage j=2 (lvl 0: 32^3 -> 64^3) ----
    bn_stage(OFF_XB, OFF_M1, 32*32*32, dec_gamma + 32, dec_beta + 32);
    k_zero<<<8192, T>>>(OFF_XA, LXC);
    k_up<<<CDIV(NS0, T), T>>>(OFF_XB, OFF_XA, dec_wup + 4096, LOFF0, 0, 64);
    k_zero<<<8192, T>>>(OFF_XB, LXC);
    k_conv3<Cn, Cn><<<CDIV(NS0, T), T>>>(OFF_XA, OFF_XB, dec_wsub3 + 13824, LOFF0, 0, 64);
    k_sparsify<<<CDIV(NS0, T), T>>>(OFF_M0, OFF_XB, 64*64*64);
    k_maskmul<<<8192, T>>>(OFF_XB, OFF_M0, 64*64*64);
    build_list(OFF_M0, OFF_M0, LOFF0, 0, NS0);
    k_zero<<<8192, T>>>(OFF_XA, LXC);
    k_conv4<<<CDIV(NS0, T), T>>>(OFF_XB, OFF_XA, dec_wsub4 + 32768, LOFF0, 0, 64);

    // ---- output conv (16->1, k3) ----
    k_zero<<<2048, T>>>(OFF_XB, NS0);
    k_conv3<Cn, 1><<<CDIV(NS0, T), T>>>(OFF_XA, OFF_XB, w_out, LOFF0, 0, 64);
    k_copy<<<4096, T>>>(outp + Cn*NS3, OFF_XB, NS0);
}